// round 10
// baseline (speedup 1.0000x reference)
#include <cuda_runtime.h>
#include <math.h>
#include <stdint.h>

#define NB 8192     // batch
#define ND 512      // dim
#define NK 4096     // codebook size
#define NL 16       // max word length

// ---------------- scratch (device globals) ---------------------------------
__device__ float g_S[(size_t)NB * NK];   // scores s0[b,k] (tf32 GEMM, nomination only)
__device__ float g_G[(size_t)NK * NK];   // gram G[i,j] (tf32 GEMM, nomination only)

// ---------------- tf32 helpers ---------------------------------------------
__device__ __forceinline__ uint32_t cvt_tf32(float x) {
    uint32_t y;
    asm("cvt.rna.tf32.f32 %0, %1;" : "=r"(y) : "f"(x));
    return y;
}
__device__ __forceinline__ void mma_tf32(float* d, const uint32_t* a,
                                         uint32_t b0, uint32_t b1) {
    asm volatile(
        "mma.sync.aligned.m16n8k8.row.col.f32.tf32.tf32.f32 "
        "{%0,%1,%2,%3}, {%4,%5,%6,%7}, {%8,%9}, {%0,%1,%2,%3};\n"
        : "+f"(d[0]), "+f"(d[1]), "+f"(d[2]), "+f"(d[3])
        : "r"(a[0]), "r"(a[1]), "r"(a[2]), "r"(a[3]), "r"(b0), "r"(b1));
}

// ---------------- merged tf32 GEMM: S = T*Cb^T and G = Cb*Cb^T -------------
// One launch; blockIdx.y < 64 -> S tile, else G tile. 128x128x32 tiles,
// 8 warps (4x2), warp tile 32x64. smem stride 36: conflict-free.
#define TBM 128
#define TBN 128
#define TBK 32
#define TST 36

__global__ __launch_bounds__(256, 2)
void tf32_gemm_both(const float* __restrict__ T, const float* __restrict__ Cb,
                    float* __restrict__ So, float* __restrict__ Go) {
    __shared__ uint32_t As[TBM][TST];
    __shared__ uint32_t Bs[TBN][TST];
    int tid = threadIdx.x;
    int lane = tid & 31, wid = tid >> 5;
    int warp_m = wid >> 1;
    int warp_n = wid & 1;
    int gid = lane >> 2;
    int tig = lane & 3;

    const float* A;
    float* Cc;
    int m0;
    if (blockIdx.y < NB / TBM) {           // S tile
        A  = T;
        Cc = So;
        m0 = blockIdx.y * TBM;
    } else {                               // G tile
        A  = Cb;
        Cc = Go;
        m0 = (blockIdx.y - NB / TBM) * TBM;
    }
    int n0 = blockIdx.x * TBN;
    const int Kd = ND, N = NK;

    float acc[2][8][4];
    #pragma unroll
    for (int i = 0; i < 2; i++)
        #pragma unroll
        for (int j = 0; j < 8; j++)
            #pragma unroll
            for (int c = 0; c < 4; c++) acc[i][j][c] = 0.f;

    for (int d0 = 0; d0 < Kd; d0 += TBK) {
        #pragma unroll
        for (int i = 0; i < 4; i++) {
            int idx = tid + i * 256;
            int r  = idx >> 3;
            int cg = (idx & 7) << 2;
            float4 va = *(const float4*)&A[(size_t)(m0 + r) * Kd + d0 + cg];
            uint4 ua = make_uint4(cvt_tf32(va.x), cvt_tf32(va.y),
                                  cvt_tf32(va.z), cvt_tf32(va.w));
            *(uint4*)&As[r][cg] = ua;
            float4 vb = *(const float4*)&Cb[(size_t)(n0 + r) * Kd + d0 + cg];
            uint4 ub = make_uint4(cvt_tf32(vb.x), cvt_tf32(vb.y),
                                  cvt_tf32(vb.z), cvt_tf32(vb.w));
            *(uint4*)&Bs[r][cg] = ub;
        }
        __syncthreads();

        #pragma unroll
        for (int k8 = 0; k8 < 4; k8++) {
            int ko = k8 * 8;
            uint32_t af[2][4];
            #pragma unroll
            for (int i = 0; i < 2; i++) {
                int mo = warp_m * 32 + i * 16;
                af[i][0] = As[mo + gid    ][ko + tig    ];
                af[i][1] = As[mo + gid + 8][ko + tig    ];
                af[i][2] = As[mo + gid    ][ko + tig + 4];
                af[i][3] = As[mo + gid + 8][ko + tig + 4];
            }
            #pragma unroll
            for (int j = 0; j < 8; j++) {
                int no = warp_n * 64 + j * 8;
                uint32_t b0 = Bs[no + gid][ko + tig    ];
                uint32_t b1 = Bs[no + gid][ko + tig + 4];
                mma_tf32(acc[0][j], af[0], b0, b1);
                mma_tf32(acc[1][j], af[1], b0, b1);
            }
        }
        __syncthreads();
    }

    #pragma unroll
    for (int i = 0; i < 2; i++) {
        int m = m0 + warp_m * 32 + i * 16 + gid;
        #pragma unroll
        for (int j = 0; j < 8; j++) {
            int n = n0 + warp_n * 64 + j * 8 + 2 * tig;
            *(float2*)&Cc[(size_t)m * N + n] =
                make_float2(acc[i][j][0], acc[i][j][1]);
            *(float2*)&Cc[(size_t)(m + 8) * N + n] =
                make_float2(acc[i][j][2], acc[i][j][3]);
        }
    }
}

// ---------------- top-2 merge (value desc, tie -> smaller index) -----------
__device__ __forceinline__ void top2_merge(float& v1, int& i1, float& v2, int& i2,
                                           float w1, int j1, float w2, int j2) {
    if (w1 > v1 || (w1 == v1 && j1 < i1)) {
        float lv = v1; int li = i1;
        v1 = w1; i1 = j1;
        if (lv > w2 || (lv == w2 && li < j2)) { v2 = lv; i2 = li; }
        else                                  { v2 = w2; i2 = j2; }
    } else {
        if (w1 > v2 || (w1 == v2 && j1 < i2)) { v2 = w1; i2 = j1; }
    }
}

// ---------------- fused pursuit: 16 steps + finalize, one kernel -----------
// Hot loop (phase 2) uses round-7's measured-fast float top-2 tracking;
// block level selects top-4 candidates from the 16 warp entries (round-9
// safety margin at zero per-element cost). Decision-path arithmetic is
// byte-identical to the passing round-9 kernel.
__global__ __launch_bounds__(256)
void pursuit_kernel(const float* __restrict__ T, const float* __restrict__ Cb,
                    const float* __restrict__ G, const float* __restrict__ S0,
                    float* __restrict__ out) {
    __shared__ float  sS[NK];            // 16 KB score row
    __shared__ float  s_r[ND];           // residual
    __shared__ float  s_q[ND];           // r / max(rho,1e-12)
    __shared__ float  s_cr[4][ND];       // staged candidate rows (8 KB)
    __shared__ double s_red[8];
    __shared__ float  s_ev[16];          // 8 warps x (v1,v2)
    __shared__ int    s_ei[16];
    __shared__ int    s_cand[4];
    __shared__ float  s_coef;
    __shared__ int    s_k;

    int b = blockIdx.x;
    int tid = threadIdx.x;
    int lane = tid & 31;
    int wid = tid >> 5;

    #pragma unroll
    for (int it = 0; it < 4; it++) {
        int k = tid * 4 + it * 1024;
        *(float4*)&sS[k] = *(const float4*)&S0[(size_t)b * NK + k];
    }
    s_r[tid]       = T[(size_t)b * ND + tid];
    s_r[tid + 256] = T[(size_t)b * ND + tid + 256];
    __syncthreads();

    int kp = 0; float cp = 0.f;
    float tn = 0.f;
    double dd = 1.0;

    for (int t = 0; t < NL; t++) {
        dd *= 0.95;                 // double cumprod (same bits as before)
        float decay = (float)dd;

        // ---- phase 1: residual update + fp64 sumsq (identical ops) -------
        double ss = 0.0;
        #pragma unroll
        for (int i = 0; i < 2; i++) {
            int d = tid + i * 256;
            float r = s_r[d];
            if (cp != 0.f) {
                float c = __ldg(&Cb[(size_t)kp * ND + d]);
                r = __fsub_rn(r, __fmul_rn(cp, c));   // unfused: matches jax
                s_r[d] = r;
            }
            s_q[d] = r;
            ss += (double)r * (double)r;
        }
        #pragma unroll
        for (int o = 16; o > 0; o >>= 1)
            ss += __shfl_down_sync(0xffffffffu, ss, o);
        if (lane == 0) s_red[wid] = ss;

        // ---- phase 2: S update (fmaf, identical) + FLOAT top-2 ----------
        float v1 = -1.f, v2 = -1.f;
        int   i1 = 0,    i2 = 0;
        const float* grow = G + (size_t)kp * NK;
        #pragma unroll
        for (int it = 0; it < 4; it++) {
            int k = tid * 4 + it * 1024;
            float4 s4 = *(float4*)&sS[k];
            if (cp != 0.f) {
                float4 g4 = __ldg((const float4*)&grow[k]);
                s4.x = fmaf(-cp, g4.x, s4.x);
                s4.y = fmaf(-cp, g4.y, s4.y);
                s4.z = fmaf(-cp, g4.z, s4.z);
                s4.w = fmaf(-cp, g4.w, s4.w);
                *(float4*)&sS[k] = s4;
            }
            float a;
            a = fabsf(s4.x); if (a > v1) { v2=v1;i2=i1; v1=a;i1=k;   } else if (a > v2) { v2=a;i2=k;   }
            a = fabsf(s4.y); if (a > v1) { v2=v1;i2=i1; v1=a;i1=k+1; } else if (a > v2) { v2=a;i2=k+1; }
            a = fabsf(s4.z); if (a > v1) { v2=v1;i2=i1; v1=a;i1=k+2; } else if (a > v2) { v2=a;i2=k+2; }
            a = fabsf(s4.w); if (a > v1) { v2=v1;i2=i1; v1=a;i1=k+3; } else if (a > v2) { v2=a;i2=k+3; }
        }
        // warp-level top-2 reduce (shuffle butterfly, round-7 code)
        #pragma unroll
        for (int o = 16; o > 0; o >>= 1) {
            float w1 = __shfl_xor_sync(0xffffffffu, v1, o);
            int   j1 = __shfl_xor_sync(0xffffffffu, i1, o);
            float w2 = __shfl_xor_sync(0xffffffffu, v2, o);
            int   j2 = __shfl_xor_sync(0xffffffffu, i2, o);
            top2_merge(v1, i1, v2, i2, w1, j1, w2, j2);
        }
        if (lane == 0) {
            s_ev[wid * 2]     = v1;  s_ei[wid * 2]     = i1;
            s_ev[wid * 2 + 1] = v2;  s_ei[wid * 2 + 1] = i2;
        }
        __syncthreads();   // B1

        // ---- rho (all threads, identical left-to-right fp64 order) ------
        double tot = s_red[0] + s_red[1] + s_red[2] + s_red[3]
                   + s_red[4] + s_red[5] + s_red[6] + s_red[7];
        float rho = sqrtf((float)tot);
        if (t == 0) tn = rho;

        // ---- top-4 candidate select from 16 warp entries (tid 0) ---------
        if (tid == 0) {
            unsigned used = 0;
            #pragma unroll
            for (int c = 0; c < 4; c++) {
                float bv = -2.f; int bi = 0; int bidx = NK;
                #pragma unroll
                for (int i = 0; i < 16; i++) {
                    if ((used >> i) & 1u) continue;
                    float v = s_ev[i]; int ix = s_ei[i];
                    if (v > bv || (v == bv && ix < bidx)) {
                        bv = v; bidx = ix; bi = i;
                    }
                }
                used |= 1u << bi;
                s_cand[c] = bidx;
            }
        }
        __syncthreads();   // B2

        // ---- q-divide (identical) + stage 4 candidate rows ---------------
        {
            float den = fmaxf(rho, 1e-12f);
            int c0 = s_cand[0], c1 = s_cand[1], c2 = s_cand[2], c3 = s_cand[3];
            #pragma unroll
            for (int i = 0; i < 2; i++) {
                int d = tid + i * 256;
                s_q[d] = __fdiv_rn(s_q[d], den);
                s_cr[0][d] = __ldg(&Cb[(size_t)c0 * ND + d]);
                s_cr[1][d] = __ldg(&Cb[(size_t)c1 * ND + d]);
                s_cr[2][d] = __ldg(&Cb[(size_t)c2 * ND + d]);
                s_cr[3][d] = __ldg(&Cb[(size_t)c3 * ND + d]);
            }
        }
        __syncthreads();   // B3

        // ---- rescore (byte-identical sequential fp32 fmaf chains) --------
        float accd = 0.f;
        if (tid < 4) {
            const float* crow = s_cr[tid];
            #pragma unroll 8
            for (int d = 0; d < ND; d++)
                accd = fmaf(s_q[d], crow[d], accd);
        }
        if (wid == 0) {
            float d0 = __shfl_sync(0xffffffffu, accd, 0);
            float d1 = __shfl_sync(0xffffffffu, accd, 1);
            float d2 = __shfl_sync(0xffffffffu, accd, 2);
            float d3 = __shfl_sync(0xffffffffu, accd, 3);
            if (lane == 0) {
                float dots[4] = {d0, d1, d2, d3};
                int bk = s_cand[0]; float sb = dots[0]; float ab = fabsf(sb);
                #pragma unroll
                for (int j = 1; j < 4; j++) {
                    float aj = fabsf(dots[j]); int kj = s_cand[j];
                    if (aj > ab || (aj == ab && kj < bk)) {
                        ab = aj; sb = dots[j]; bk = kj;
                    }
                }
                bool active = (rho >= 0.01f) && (tn >= 1e-8f);
                float sgn = (sb >= 0.f) ? 1.f : -1.f;
                int sidx  = (sb >= 0.f) ? bk : -(bk + 1);
                out[b * NL + t]           = (float)(active ? sidx : 0);
                out[NB * NL + b * NL + t] = active ? 1.f : 0.f;
                s_k = bk;
                s_coef = active ? __fmul_rn(sgn, decay) : 0.f;
            }
        }
        __syncthreads();   // B4
        kp = s_k;
        cp = s_coef;
    }

    // ---- epilogue: apply FINAL step's contribution (identical ops) -------
    float r0 = s_r[tid];
    float r1 = s_r[tid + 256];
    if (cp != 0.f) {
        float c0 = __ldg(&Cb[(size_t)kp * ND + tid]);
        float c1 = __ldg(&Cb[(size_t)kp * ND + tid + 256]);
        r0 = __fsub_rn(r0, __fmul_rn(cp, c0));
        r1 = __fsub_rn(r1, __fmul_rn(cp, c1));
    }
    float* out_res = out + (size_t)2 * NB * NL;
    out_res[(size_t)b * ND + tid]       = r0;
    out_res[(size_t)b * ND + tid + 256] = r1;
}

// ---------------- launch ----------------------------------------------------
extern "C" void kernel_launch(void* const* d_in, const int* in_sizes, int n_in,
                              void* d_out, int out_size) {
    const float* targets  = (const float*)d_in[0];  // [8192, 512]
    const float* codebook = (const float*)d_in[1];  // [4096, 512]
    float* out = (float*)d_out;

    float *pS, *pG;
    cudaGetSymbolAddress((void**)&pS, g_S);
    cudaGetSymbolAddress((void**)&pG, g_G);

    // merged S + G GEMM: 64 S-row-tiles then 32 G-row-tiles in one launch
    dim3 gAll(NK / TBN, NB / TBM + NK / TBM);
    tf32_gemm_both<<<gAll, 256>>>(targets, codebook, pS, pG);

    pursuit_kernel<<<NB, 256>>>(targets, codebook, pG, pS, out);
}

// round 11
// speedup vs baseline: 1.0002x; 1.0002x over previous
#include <cuda_runtime.h>
#include <math.h>
#include <stdint.h>

#define NB 8192     // batch
#define ND 512      // dim
#define NK 4096     // codebook size
#define NL 16       // max word length

// ---------------- scratch (device globals) ---------------------------------
__device__ float g_S[(size_t)NB * NK];   // scores s0[b,k] (tf32 GEMM, nomination only)
__device__ float g_G[(size_t)NK * NK];   // gram G[i,j] (tf32 GEMM, nomination only)

// ---------------- tf32 helpers ---------------------------------------------
__device__ __forceinline__ uint32_t cvt_tf32(float x) {
    uint32_t y;
    asm("cvt.rna.tf32.f32 %0, %1;" : "=r"(y) : "f"(x));
    return y;
}
__device__ __forceinline__ void mma_tf32(float* d, const uint32_t* a,
                                         uint32_t b0, uint32_t b1) {
    asm volatile(
        "mma.sync.aligned.m16n8k8.row.col.f32.tf32.tf32.f32 "
        "{%0,%1,%2,%3}, {%4,%5,%6,%7}, {%8,%9}, {%0,%1,%2,%3};\n"
        : "+f"(d[0]), "+f"(d[1]), "+f"(d[2]), "+f"(d[3])
        : "r"(a[0]), "r"(a[1]), "r"(a[2]), "r"(a[3]), "r"(b0), "r"(b1));
}

// ---------------- tf32 GEMM (NT): C[M,N] = A[M,K] * B[N,K]^T ---------------
// (round-9 kernel, measured 234+117 us as two separate launches)
#define TBM 128
#define TBN 128
#define TBK 32
#define TST 36

__global__ __launch_bounds__(256, 2)
void tf32_gemm_nt(const float* __restrict__ A, const float* __restrict__ Bm,
                  float* __restrict__ Cc, int M, int N, int Kd) {
    __shared__ uint32_t As[TBM][TST];
    __shared__ uint32_t Bs[TBN][TST];
    int tid = threadIdx.x;
    int lane = tid & 31, wid = tid >> 5;
    int warp_m = wid >> 1;
    int warp_n = wid & 1;
    int gid = lane >> 2;
    int tig = lane & 3;
    int m0 = blockIdx.y * TBM, n0 = blockIdx.x * TBN;

    float acc[2][8][4];
    #pragma unroll
    for (int i = 0; i < 2; i++)
        #pragma unroll
        for (int j = 0; j < 8; j++)
            #pragma unroll
            for (int c = 0; c < 4; c++) acc[i][j][c] = 0.f;

    for (int d0 = 0; d0 < Kd; d0 += TBK) {
        #pragma unroll
        for (int i = 0; i < 4; i++) {
            int idx = tid + i * 256;
            int r  = idx >> 3;
            int cg = (idx & 7) << 2;
            float4 va = *(const float4*)&A[(size_t)(m0 + r) * Kd + d0 + cg];
            uint4 ua = make_uint4(cvt_tf32(va.x), cvt_tf32(va.y),
                                  cvt_tf32(va.z), cvt_tf32(va.w));
            *(uint4*)&As[r][cg] = ua;
            float4 vb = *(const float4*)&Bm[(size_t)(n0 + r) * Kd + d0 + cg];
            uint4 ub = make_uint4(cvt_tf32(vb.x), cvt_tf32(vb.y),
                                  cvt_tf32(vb.z), cvt_tf32(vb.w));
            *(uint4*)&Bs[r][cg] = ub;
        }
        __syncthreads();

        #pragma unroll
        for (int k8 = 0; k8 < 4; k8++) {
            int ko = k8 * 8;
            uint32_t af[2][4];
            #pragma unroll
            for (int i = 0; i < 2; i++) {
                int mo = warp_m * 32 + i * 16;
                af[i][0] = As[mo + gid    ][ko + tig    ];
                af[i][1] = As[mo + gid + 8][ko + tig    ];
                af[i][2] = As[mo + gid    ][ko + tig + 4];
                af[i][3] = As[mo + gid + 8][ko + tig + 4];
            }
            #pragma unroll
            for (int j = 0; j < 8; j++) {
                int no = warp_n * 64 + j * 8;
                uint32_t b0 = Bs[no + gid][ko + tig    ];
                uint32_t b1 = Bs[no + gid][ko + tig + 4];
                mma_tf32(acc[0][j], af[0], b0, b1);
                mma_tf32(acc[1][j], af[1], b0, b1);
            }
        }
        __syncthreads();
    }

    #pragma unroll
    for (int i = 0; i < 2; i++) {
        int m = m0 + warp_m * 32 + i * 16 + gid;
        #pragma unroll
        for (int j = 0; j < 8; j++) {
            int n = n0 + warp_n * 64 + j * 8 + 2 * tig;
            *(float2*)&Cc[(size_t)m * N + n] =
                make_float2(acc[i][j][0], acc[i][j][1]);
            *(float2*)&Cc[(size_t)(m + 8) * N + n] =
                make_float2(acc[i][j][2], acc[i][j][3]);
        }
    }
}

// ---------------- top-2 merge (value desc, tie -> smaller index) -----------
__device__ __forceinline__ void top2_merge(float& v1, int& i1, float& v2, int& i2,
                                           float w1, int j1, float w2, int j2) {
    if (w1 > v1 || (w1 == v1 && j1 < i1)) {
        float lv = v1; int li = i1;
        v1 = w1; i1 = j1;
        if (lv > w2 || (lv == w2 && li < j2)) { v2 = lv; i2 = li; }
        else                                  { v2 = w2; i2 = j2; }
    } else {
        if (w1 > v2 || (w1 == v2 && j1 < i2)) { v2 = w1; i2 = j1; }
    }
}

// ---------------- fused pursuit: 16 steps + finalize, one kernel -----------
// R10's pursuit (float top-2 hot loop + top-4 block select). Decision-path
// arithmetic byte-identical to rounds 9/10 (both rel_err 1.896267e-07).
__global__ __launch_bounds__(256)
void pursuit_kernel(const float* __restrict__ T, const float* __restrict__ Cb,
                    const float* __restrict__ G, const float* __restrict__ S0,
                    float* __restrict__ out) {
    __shared__ float  sS[NK];            // 16 KB score row
    __shared__ float  s_r[ND];           // residual
    __shared__ float  s_q[ND];           // r / max(rho,1e-12)
    __shared__ float  s_cr[4][ND];       // staged candidate rows (8 KB)
    __shared__ double s_red[8];
    __shared__ float  s_ev[16];          // 8 warps x (v1,v2)
    __shared__ int    s_ei[16];
    __shared__ int    s_cand[4];
    __shared__ float  s_coef;
    __shared__ int    s_k;

    int b = blockIdx.x;
    int tid = threadIdx.x;
    int lane = tid & 31;
    int wid = tid >> 5;

    #pragma unroll
    for (int it = 0; it < 4; it++) {
        int k = tid * 4 + it * 1024;
        *(float4*)&sS[k] = *(const float4*)&S0[(size_t)b * NK + k];
    }
    s_r[tid]       = T[(size_t)b * ND + tid];
    s_r[tid + 256] = T[(size_t)b * ND + tid + 256];
    __syncthreads();

    int kp = 0; float cp = 0.f;
    float tn = 0.f;
    double dd = 1.0;

    for (int t = 0; t < NL; t++) {
        dd *= 0.95;                 // double cumprod (same bits as before)
        float decay = (float)dd;

        // ---- phase 1: residual update + fp64 sumsq (identical ops) -------
        double ss = 0.0;
        #pragma unroll
        for (int i = 0; i < 2; i++) {
            int d = tid + i * 256;
            float r = s_r[d];
            if (cp != 0.f) {
                float c = __ldg(&Cb[(size_t)kp * ND + d]);
                r = __fsub_rn(r, __fmul_rn(cp, c));   // unfused: matches jax
                s_r[d] = r;
            }
            s_q[d] = r;
            ss += (double)r * (double)r;
        }
        #pragma unroll
        for (int o = 16; o > 0; o >>= 1)
            ss += __shfl_down_sync(0xffffffffu, ss, o);
        if (lane == 0) s_red[wid] = ss;

        // ---- phase 2: S update (fmaf, identical) + FLOAT top-2 ----------
        float v1 = -1.f, v2 = -1.f;
        int   i1 = 0,    i2 = 0;
        const float* grow = G + (size_t)kp * NK;
        #pragma unroll
        for (int it = 0; it < 4; it++) {
            int k = tid * 4 + it * 1024;
            float4 s4 = *(float4*)&sS[k];
            if (cp != 0.f) {
                float4 g4 = __ldg((const float4*)&grow[k]);
                s4.x = fmaf(-cp, g4.x, s4.x);
                s4.y = fmaf(-cp, g4.y, s4.y);
                s4.z = fmaf(-cp, g4.z, s4.z);
                s4.w = fmaf(-cp, g4.w, s4.w);
                *(float4*)&sS[k] = s4;
            }
            float a;
            a = fabsf(s4.x); if (a > v1) { v2=v1;i2=i1; v1=a;i1=k;   } else if (a > v2) { v2=a;i2=k;   }
            a = fabsf(s4.y); if (a > v1) { v2=v1;i2=i1; v1=a;i1=k+1; } else if (a > v2) { v2=a;i2=k+1; }
            a = fabsf(s4.z); if (a > v1) { v2=v1;i2=i1; v1=a;i1=k+2; } else if (a > v2) { v2=a;i2=k+2; }
            a = fabsf(s4.w); if (a > v1) { v2=v1;i2=i1; v1=a;i1=k+3; } else if (a > v2) { v2=a;i2=k+3; }
        }
        // warp-level top-2 reduce (shuffle butterfly)
        #pragma unroll
        for (int o = 16; o > 0; o >>= 1) {
            float w1 = __shfl_xor_sync(0xffffffffu, v1, o);
            int   j1 = __shfl_xor_sync(0xffffffffu, i1, o);
            float w2 = __shfl_xor_sync(0xffffffffu, v2, o);
            int   j2 = __shfl_xor_sync(0xffffffffu, i2, o);
            top2_merge(v1, i1, v2, i2, w1, j1, w2, j2);
        }
        if (lane == 0) {
            s_ev[wid * 2]     = v1;  s_ei[wid * 2]     = i1;
            s_ev[wid * 2 + 1] = v2;  s_ei[wid * 2 + 1] = i2;
        }
        __syncthreads();   // B1

        // ---- rho (all threads, identical left-to-right fp64 order) ------
        double tot = s_red[0] + s_red[1] + s_red[2] + s_red[3]
                   + s_red[4] + s_red[5] + s_red[6] + s_red[7];
        float rho = sqrtf((float)tot);
        if (t == 0) tn = rho;

        // ---- top-4 candidate select from 16 warp entries (tid 0) ---------
        if (tid == 0) {
            unsigned used = 0;
            #pragma unroll
            for (int c = 0; c < 4; c++) {
                float bv = -2.f; int bi = 0; int bidx = NK;
                #pragma unroll
                for (int i = 0; i < 16; i++) {
                    if ((used >> i) & 1u) continue;
                    float v = s_ev[i]; int ix = s_ei[i];
                    if (v > bv || (v == bv && ix < bidx)) {
                        bv = v; bidx = ix; bi = i;
                    }
                }
                used |= 1u << bi;
                s_cand[c] = bidx;
            }
        }
        __syncthreads();   // B2

        // ---- q-divide (identical) + stage 4 candidate rows ---------------
        {
            float den = fmaxf(rho, 1e-12f);
            int c0 = s_cand[0], c1 = s_cand[1], c2 = s_cand[2], c3 = s_cand[3];
            #pragma unroll
            for (int i = 0; i < 2; i++) {
                int d = tid + i * 256;
                s_q[d] = __fdiv_rn(s_q[d], den);
                s_cr[0][d] = __ldg(&Cb[(size_t)c0 * ND + d]);
                s_cr[1][d] = __ldg(&Cb[(size_t)c1 * ND + d]);
                s_cr[2][d] = __ldg(&Cb[(size_t)c2 * ND + d]);
                s_cr[3][d] = __ldg(&Cb[(size_t)c3 * ND + d]);
            }
        }
        __syncthreads();   // B3

        // ---- rescore (byte-identical sequential fp32 fmaf chains) --------
        float accd = 0.f;
        if (tid < 4) {
            const float* crow = s_cr[tid];
            #pragma unroll 8
            for (int d = 0; d < ND; d++)
                accd = fmaf(s_q[d], crow[d], accd);
        }
        if (wid == 0) {
            float d0 = __shfl_sync(0xffffffffu, accd, 0);
            float d1 = __shfl_sync(0xffffffffu, accd, 1);
            float d2 = __shfl_sync(0xffffffffu, accd, 2);
            float d3 = __shfl_sync(0xffffffffu, accd, 3);
            if (lane == 0) {
                float dots[4] = {d0, d1, d2, d3};
                int bk = s_cand[0]; float sb = dots[0]; float ab = fabsf(sb);
                #pragma unroll
                for (int j = 1; j < 4; j++) {
                    float aj = fabsf(dots[j]); int kj = s_cand[j];
                    if (aj > ab || (aj == ab && kj < bk)) {
                        ab = aj; sb = dots[j]; bk = kj;
                    }
                }
                bool active = (rho >= 0.01f) && (tn >= 1e-8f);
                float sgn = (sb >= 0.f) ? 1.f : -1.f;
                int sidx  = (sb >= 0.f) ? bk : -(bk + 1);
                out[b * NL + t]           = (float)(active ? sidx : 0);
                out[NB * NL + b * NL + t] = active ? 1.f : 0.f;
                s_k = bk;
                s_coef = active ? __fmul_rn(sgn, decay) : 0.f;
            }
        }
        __syncthreads();   // B4
        kp = s_k;
        cp = s_coef;
    }

    // ---- epilogue: apply FINAL step's contribution (identical ops) -------
    float r0 = s_r[tid];
    float r1 = s_r[tid + 256];
    if (cp != 0.f) {
        float c0 = __ldg(&Cb[(size_t)kp * ND + tid]);
        float c1 = __ldg(&Cb[(size_t)kp * ND + tid + 256]);
        r0 = __fsub_rn(r0, __fmul_rn(cp, c0));
        r1 = __fsub_rn(r1, __fmul_rn(cp, c1));
    }
    float* out_res = out + (size_t)2 * NB * NL;
    out_res[(size_t)b * ND + tid]       = r0;
    out_res[(size_t)b * ND + tid + 256] = r1;
}

// ---------------- launch ----------------------------------------------------
extern "C" void kernel_launch(void* const* d_in, const int* in_sizes, int n_in,
                              void* d_out, int out_size) {
    const float* targets  = (const float*)d_in[0];  // [8192, 512]
    const float* codebook = (const float*)d_in[1];  // [4096, 512]
    float* out = (float*)d_out;

    float *pS, *pG;
    cudaGetSymbolAddress((void**)&pS, g_S);
    cudaGetSymbolAddress((void**)&pG, g_G);

    // separate launches (round-9 config; merged version regressed in R10)
    dim3 gS(NK / TBN, NB / TBM);
    tf32_gemm_nt<<<gS, 256>>>(targets, codebook, pS, NB, NK, ND);

    dim3 gG(NK / TBN, NK / TBM);
    tf32_gemm_nt<<<gG, 256>>>(codebook, codebook, pG, NK, NK, ND);

    pursuit_kernel<<<NB, 256>>>(targets, codebook, pG, pS, out);
}

// round 12
// speedup vs baseline: 1.0067x; 1.0064x over previous
#include <cuda_runtime.h>
#include <math.h>
#include <stdint.h>

#define NB 8192     // batch
#define ND 512      // dim
#define NK 4096     // codebook size
#define NL 16       // max word length

// ---------------- scratch (device globals) ---------------------------------
__device__ float g_S[(size_t)NB * NK];   // scores s0[b,k] (tf32 GEMM, nomination only)
__device__ float g_G[(size_t)NK * NK];   // gram G[i,j] (tf32 GEMM, nomination only)

// ---------------- tf32 helpers ---------------------------------------------
__device__ __forceinline__ uint32_t cvt_tf32(float x) {
    uint32_t y;
    asm("cvt.rna.tf32.f32 %0, %1;" : "=r"(y) : "f"(x));
    return y;
}
__device__ __forceinline__ void mma_tf32(float* d, const uint32_t* a,
                                         uint32_t b0, uint32_t b1) {
    asm volatile(
        "mma.sync.aligned.m16n8k8.row.col.f32.tf32.tf32.f32 "
        "{%0,%1,%2,%3}, {%4,%5,%6,%7}, {%8,%9}, {%0,%1,%2,%3};\n"
        : "+f"(d[0]), "+f"(d[1]), "+f"(d[2]), "+f"(d[3])
        : "r"(a[0]), "r"(a[1]), "r"(a[2]), "r"(a[3]), "r"(b0), "r"(b1));
}

// ---------------- tf32 GEMM (NT): C[M,N] = A[M,K] * B[N,K]^T ---------------
// (round-9 kernel, measured 234+117 us as separate launches)
#define TBM 128
#define TBN 128
#define TBK 32
#define TST 36

__global__ __launch_bounds__(256, 2)
void tf32_gemm_nt(const float* __restrict__ A, const float* __restrict__ Bm,
                  float* __restrict__ Cc, int M, int N, int Kd) {
    __shared__ uint32_t As[TBM][TST];
    __shared__ uint32_t Bs[TBN][TST];
    int tid = threadIdx.x;
    int lane = tid & 31, wid = tid >> 5;
    int warp_m = wid >> 1;
    int warp_n = wid & 1;
    int gid = lane >> 2;
    int tig = lane & 3;
    int m0 = blockIdx.y * TBM, n0 = blockIdx.x * TBN;

    float acc[2][8][4];
    #pragma unroll
    for (int i = 0; i < 2; i++)
        #pragma unroll
        for (int j = 0; j < 8; j++)
            #pragma unroll
            for (int c = 0; c < 4; c++) acc[i][j][c] = 0.f;

    for (int d0 = 0; d0 < Kd; d0 += TBK) {
        #pragma unroll
        for (int i = 0; i < 4; i++) {
            int idx = tid + i * 256;
            int r  = idx >> 3;
            int cg = (idx & 7) << 2;
            float4 va = *(const float4*)&A[(size_t)(m0 + r) * Kd + d0 + cg];
            uint4 ua = make_uint4(cvt_tf32(va.x), cvt_tf32(va.y),
                                  cvt_tf32(va.z), cvt_tf32(va.w));
            *(uint4*)&As[r][cg] = ua;
            float4 vb = *(const float4*)&Bm[(size_t)(n0 + r) * Kd + d0 + cg];
            uint4 ub = make_uint4(cvt_tf32(vb.x), cvt_tf32(vb.y),
                                  cvt_tf32(vb.z), cvt_tf32(vb.w));
            *(uint4*)&Bs[r][cg] = ub;
        }
        __syncthreads();

        #pragma unroll
        for (int k8 = 0; k8 < 4; k8++) {
            int ko = k8 * 8;
            uint32_t af[2][4];
            #pragma unroll
            for (int i = 0; i < 2; i++) {
                int mo = warp_m * 32 + i * 16;
                af[i][0] = As[mo + gid    ][ko + tig    ];
                af[i][1] = As[mo + gid + 8][ko + tig    ];
                af[i][2] = As[mo + gid    ][ko + tig + 4];
                af[i][3] = As[mo + gid + 8][ko + tig + 4];
            }
            #pragma unroll
            for (int j = 0; j < 8; j++) {
                int no = warp_n * 64 + j * 8;
                uint32_t b0 = Bs[no + gid][ko + tig    ];
                uint32_t b1 = Bs[no + gid][ko + tig + 4];
                mma_tf32(acc[0][j], af[0], b0, b1);
                mma_tf32(acc[1][j], af[1], b0, b1);
            }
        }
        __syncthreads();
    }

    #pragma unroll
    for (int i = 0; i < 2; i++) {
        int m = m0 + warp_m * 32 + i * 16 + gid;
        #pragma unroll
        for (int j = 0; j < 8; j++) {
            int n = n0 + warp_n * 64 + j * 8 + 2 * tig;
            *(float2*)&Cc[(size_t)m * N + n] =
                make_float2(acc[i][j][0], acc[i][j][1]);
            *(float2*)&Cc[(size_t)(m + 8) * N + n] =
                make_float2(acc[i][j][2], acc[i][j][3]);
        }
    }
}

// ---------------- fused pursuit: 16 steps + finalize, one kernel -----------
// R9's u64 hot loop (measured fastest) + latency cuts:
//  - G-row float4 loads batched (MLP=4) ahead of the S-update chain
//  - rho + top-4 select computed redundantly by ALL threads (kills a barrier)
//  - phase-1 residual update reads chosen codebook row from staged smem
// Decision-path arithmetic byte-identical to round 9 (rel_err 1.896267e-07).
__global__ __launch_bounds__(256, 4)
void pursuit_kernel(const float* __restrict__ T, const float* __restrict__ Cb,
                    const float* __restrict__ G, const float* __restrict__ S0,
                    float* __restrict__ out) {
    __shared__ float  sS[NK];            // 16 KB score row
    __shared__ float  s_r[ND];           // residual
    __shared__ float  s_q[ND];           // r / max(rho,1e-12)
    __shared__ float  s_cr[4][ND];       // staged candidate rows (8 KB)
    __shared__ double s_red[8];
    __shared__ unsigned long long s_w64[16];
    __shared__ float  s_coef;
    __shared__ int    s_k, s_jwin;

    int b = blockIdx.x;
    int tid = threadIdx.x;
    int lane = tid & 31;
    int wid = tid >> 5;

    #pragma unroll
    for (int it = 0; it < 4; it++) {
        int k = tid * 4 + it * 1024;
        *(float4*)&sS[k] = *(const float4*)&S0[(size_t)b * NK + k];
    }
    s_r[tid]       = T[(size_t)b * ND + tid];
    s_r[tid + 256] = T[(size_t)b * ND + tid + 256];
    __syncthreads();

    int kp = 0, jwl = 0;
    float cp = 0.f;
    float tn = 0.f;
    double dd = 1.0;

    for (int t = 0; t < NL; t++) {
        dd *= 0.95;                 // double cumprod (same bits as before)
        float decay = (float)dd;

        // ---- phase 1: residual update (staged smem row; identical bits) --
        double ss = 0.0;
        #pragma unroll
        for (int i = 0; i < 2; i++) {
            int d = tid + i * 256;
            float r = s_r[d];
            if (cp != 0.f) {
                float c = s_cr[jwl][d];               // == Cb[kp*ND+d] bits
                r = __fsub_rn(r, __fmul_rn(cp, c));   // unfused: matches jax
                s_r[d] = r;
            }
            s_q[d] = r;
            ss += (double)r * (double)r;
        }
        #pragma unroll
        for (int o = 16; o > 0; o >>= 1)
            ss += __shfl_down_sync(0xffffffffu, ss, o);
        if (lane == 0) s_red[wid] = ss;

        // ---- phase 2: batched G loads, S update (fmaf), u64 top-2 --------
        const float* grow = G + (size_t)kp * NK;
        float4 g4[4];
        if (cp != 0.f) {
            #pragma unroll
            for (int it = 0; it < 4; it++)
                g4[it] = __ldg((const float4*)&grow[tid * 4 + it * 1024]);
        }
        unsigned long long p1 = 0ull, p2 = 0ull;
        #pragma unroll
        for (int it = 0; it < 4; it++) {
            int k = tid * 4 + it * 1024;
            float4 s4 = *(float4*)&sS[k];
            if (cp != 0.f) {
                s4.x = fmaf(-cp, g4[it].x, s4.x);
                s4.y = fmaf(-cp, g4[it].y, s4.y);
                s4.z = fmaf(-cp, g4[it].z, s4.z);
                s4.w = fmaf(-cp, g4[it].w, s4.w);
                *(float4*)&sS[k] = s4;
            }
            #pragma unroll
            for (int e = 0; e < 4; e++) {
                float a = fabsf((&s4.x)[e]);
                unsigned long long u =
                    ((unsigned long long)__float_as_uint(a) << 32) |
                    (unsigned)(NK - 1 - (k + e));
                if (u > p1)      { p2 = p1; p1 = u; }
                else if (u > p2) { p2 = u; }
            }
        }
        #pragma unroll
        for (int o = 16; o > 0; o >>= 1) {
            unsigned long long q1 = __shfl_xor_sync(0xffffffffu, p1, o);
            unsigned long long q2 = __shfl_xor_sync(0xffffffffu, p2, o);
            if (q1 > p1) { p2 = (p1 > q2) ? p1 : q2; p1 = q1; }
            else         { p2 = (p2 > q1) ? p2 : q1; }
        }
        if (lane == 0) {
            s_w64[wid * 2]     = p1;
            s_w64[wid * 2 + 1] = p2;
        }
        __syncthreads();   // B1

        // ---- rho + top-4 select: ALL threads redundantly (same result) ---
        double tot = s_red[0] + s_red[1] + s_red[2] + s_red[3]
                   + s_red[4] + s_red[5] + s_red[6] + s_red[7];
        float rho = sqrtf((float)tot);
        if (t == 0) tn = rho;

        int cand[4];
        {
            unsigned used = 0;
            #pragma unroll
            for (int c = 0; c < 4; c++) {
                unsigned long long best = 0ull; int bi = 0;
                #pragma unroll
                for (int i = 0; i < 16; i++) {
                    if (!((used >> i) & 1u) && s_w64[i] > best) {
                        best = s_w64[i]; bi = i;
                    }
                }
                used |= 1u << bi;
                cand[c] = (NK - 1) - (int)(unsigned)(best & 0xffffffffull);
            }
        }

        // ---- q-divide (identical) + stage 4 candidate rows ---------------
        {
            float den = fmaxf(rho, 1e-12f);
            #pragma unroll
            for (int i = 0; i < 2; i++) {
                int d = tid + i * 256;
                s_q[d] = __fdiv_rn(s_q[d], den);
                s_cr[0][d] = __ldg(&Cb[(size_t)cand[0] * ND + d]);
                s_cr[1][d] = __ldg(&Cb[(size_t)cand[1] * ND + d]);
                s_cr[2][d] = __ldg(&Cb[(size_t)cand[2] * ND + d]);
                s_cr[3][d] = __ldg(&Cb[(size_t)cand[3] * ND + d]);
            }
        }
        __syncthreads();   // B2

        // ---- rescore (byte-identical sequential fp32 fmaf chains) --------
        float accd = 0.f;
        if (tid < 4) {
            const float* crow = s_cr[tid];
            #pragma unroll 8
            for (int d = 0; d < ND; d++)
                accd = fmaf(s_q[d], crow[d], accd);
        }
        if (wid == 0) {
            float d0 = __shfl_sync(0xffffffffu, accd, 0);
            float d1 = __shfl_sync(0xffffffffu, accd, 1);
            float d2 = __shfl_sync(0xffffffffu, accd, 2);
            float d3 = __shfl_sync(0xffffffffu, accd, 3);
            if (lane == 0) {
                float dots[4] = {d0, d1, d2, d3};
                int bk = cand[0]; float sb = dots[0]; float ab = fabsf(sb);
                int jw = 0;
                #pragma unroll
                for (int j = 1; j < 4; j++) {
                    float aj = fabsf(dots[j]); int kj = cand[j];
                    if (aj > ab || (aj == ab && kj < bk)) {
                        ab = aj; sb = dots[j]; bk = kj; jw = j;
                    }
                }
                bool active = (rho >= 0.01f) && (tn >= 1e-8f);
                float sgn = (sb >= 0.f) ? 1.f : -1.f;
                int sidx  = (sb >= 0.f) ? bk : -(bk + 1);
                out[b * NL + t]           = (float)(active ? sidx : 0);
                out[NB * NL + b * NL + t] = active ? 1.f : 0.f;
                s_k = bk;
                s_jwin = jw;
                s_coef = active ? __fmul_rn(sgn, decay) : 0.f;
            }
        }
        __syncthreads();   // B3
        kp  = s_k;
        jwl = s_jwin;
        cp  = s_coef;
    }

    // ---- epilogue: apply FINAL step's contribution (identical bits) ------
    float r0 = s_r[tid];
    float r1 = s_r[tid + 256];
    if (cp != 0.f) {
        float c0 = s_cr[jwl][tid];
        float c1 = s_cr[jwl][tid + 256];
        r0 = __fsub_rn(r0, __fmul_rn(cp, c0));
        r1 = __fsub_rn(r1, __fmul_rn(cp, c1));
    }
    float* out_res = out + (size_t)2 * NB * NL;
    out_res[(size_t)b * ND + tid]       = r0;
    out_res[(size_t)b * ND + tid + 256] = r1;
}

// ---------------- launch ----------------------------------------------------
extern "C" void kernel_launch(void* const* d_in, const int* in_sizes, int n_in,
                              void* d_out, int out_size) {
    const float* targets  = (const float*)d_in[0];  // [8192, 512]
    const float* codebook = (const float*)d_in[1];  // [4096, 512]
    float* out = (float*)d_out;

    float *pS, *pG;
    cudaGetSymbolAddress((void**)&pS, g_S);
    cudaGetSymbolAddress((void**)&pG, g_G);

    dim3 gS(NK / TBN, NB / TBM);
    tf32_gemm_nt<<<gS, 256>>>(targets, codebook, pS, NB, NK, ND);

    dim3 gG(NK / TBN, NK / TBM);
    tf32_gemm_nt<<<gG, 256>>>(codebook, codebook, pG, NK, NK, ND);

    pursuit_kernel<<<NB, 256>>>(targets, codebook, pG, pS, out);
}

// round 14
// speedup vs baseline: 1.2204x; 1.2123x over previous
#include <cuda_runtime.h>
#include <math.h>
#include <stdint.h>

#define NB 8192     // batch
#define ND 512      // dim
#define NK 4096     // codebook size
#define NL 16       // max word length

// ---------------- scratch (device globals) ---------------------------------
__device__ float g_S[(size_t)NB * NK];   // scores s0[b,k] (tf32 GEMM, nomination only)
__device__ float g_G[(size_t)NK * NK];   // gram G[i,j] (tf32 GEMM, nomination only)

// ---------------- tf32 helpers ---------------------------------------------
__device__ __forceinline__ uint32_t cvt_tf32(float x) {
    uint32_t y;
    asm("cvt.rna.tf32.f32 %0, %1;" : "=r"(y) : "f"(x));
    return y;
}
__device__ __forceinline__ void mma_tf32(float* d, const uint32_t* a,
                                         uint32_t b0, uint32_t b1) {
    asm volatile(
        "mma.sync.aligned.m16n8k8.row.col.f32.tf32.tf32.f32 "
        "{%0,%1,%2,%3}, {%4,%5,%6,%7}, {%8,%9}, {%0,%1,%2,%3};\n"
        : "+f"(d[0]), "+f"(d[1]), "+f"(d[2]), "+f"(d[3])
        : "r"(a[0]), "r"(a[1]), "r"(a[2]), "r"(a[3]), "r"(b0), "r"(b1));
}

// ---------------- tf32 GEMM (NT): C[M,N] = A[M,K] * B[N,K]^T ---------------
// (round-9 kernel, measured 234+117 us as separate launches)
#define TBM 128
#define TBN 128
#define TBK 32
#define TST 36

__global__ __launch_bounds__(256, 2)
void tf32_gemm_nt(const float* __restrict__ A, const float* __restrict__ Bm,
                  float* __restrict__ Cc, int M, int N, int Kd) {
    __shared__ uint32_t As[TBM][TST];
    __shared__ uint32_t Bs[TBN][TST];
    int tid = threadIdx.x;
    int lane = tid & 31, wid = tid >> 5;
    int warp_m = wid >> 1;
    int warp_n = wid & 1;
    int gid = lane >> 2;
    int tig = lane & 3;
    int m0 = blockIdx.y * TBM, n0 = blockIdx.x * TBN;

    float acc[2][8][4];
    #pragma unroll
    for (int i = 0; i < 2; i++)
        #pragma unroll
        for (int j = 0; j < 8; j++)
            #pragma unroll
            for (int c = 0; c < 4; c++) acc[i][j][c] = 0.f;

    for (int d0 = 0; d0 < Kd; d0 += TBK) {
        #pragma unroll
        for (int i = 0; i < 4; i++) {
            int idx = tid + i * 256;
            int r  = idx >> 3;
            int cg = (idx & 7) << 2;
            float4 va = *(const float4*)&A[(size_t)(m0 + r) * Kd + d0 + cg];
            uint4 ua = make_uint4(cvt_tf32(va.x), cvt_tf32(va.y),
                                  cvt_tf32(va.z), cvt_tf32(va.w));
            *(uint4*)&As[r][cg] = ua;
            float4 vb = *(const float4*)&Bm[(size_t)(n0 + r) * Kd + d0 + cg];
            uint4 ub = make_uint4(cvt_tf32(vb.x), cvt_tf32(vb.y),
                                  cvt_tf32(vb.z), cvt_tf32(vb.w));
            *(uint4*)&Bs[r][cg] = ub;
        }
        __syncthreads();

        #pragma unroll
        for (int k8 = 0; k8 < 4; k8++) {
            int ko = k8 * 8;
            uint32_t af[2][4];
            #pragma unroll
            for (int i = 0; i < 2; i++) {
                int mo = warp_m * 32 + i * 16;
                af[i][0] = As[mo + gid    ][ko + tig    ];
                af[i][1] = As[mo + gid + 8][ko + tig    ];
                af[i][2] = As[mo + gid    ][ko + tig + 4];
                af[i][3] = As[mo + gid + 8][ko + tig + 4];
            }
            #pragma unroll
            for (int j = 0; j < 8; j++) {
                int no = warp_n * 64 + j * 8;
                uint32_t b0 = Bs[no + gid][ko + tig    ];
                uint32_t b1 = Bs[no + gid][ko + tig + 4];
                mma_tf32(acc[0][j], af[0], b0, b1);
                mma_tf32(acc[1][j], af[1], b0, b1);
            }
        }
        __syncthreads();
    }

    #pragma unroll
    for (int i = 0; i < 2; i++) {
        int m = m0 + warp_m * 32 + i * 16 + gid;
        #pragma unroll
        for (int j = 0; j < 8; j++) {
            int n = n0 + warp_n * 64 + j * 8 + 2 * tig;
            *(float2*)&Cc[(size_t)m * N + n] =
                make_float2(acc[i][j][0], acc[i][j][1]);
            *(float2*)&Cc[(size_t)(m + 8) * N + n] =
                make_float2(acc[i][j][2], acc[i][j][3]);
        }
    }
}

// ---------------- fused pursuit: 16 steps + finalize, one kernel -----------
// EXACT round-9 pursuit body (best measured: ~1600 us). Sole change:
// __launch_bounds__(256, 5) -> 48-reg cap -> 5 blocks/SM instead of 4
// (RF was the occupancy limiter at regs=64; smem 28.9KB*5 = 145KB fits).
// Decision-path arithmetic byte-identical to round 9 (rel_err 1.896267e-07).
__global__ __launch_bounds__(256, 5)
void pursuit_kernel(const float* __restrict__ T, const float* __restrict__ Cb,
                    const float* __restrict__ G, const float* __restrict__ S0,
                    float* __restrict__ out) {
    __shared__ float  sS[NK];            // 16 KB score row
    __shared__ float  s_r[ND];           // residual
    __shared__ float  s_q[ND];           // r / max(rho,1e-12)
    __shared__ float  s_cr[4][ND];       // staged candidate rows (8 KB)
    __shared__ double s_red[8];
    __shared__ unsigned long long s_w64[16];
    __shared__ int    s_cand[4];
    __shared__ float  s_coef;
    __shared__ int    s_k;

    int b = blockIdx.x;
    int tid = threadIdx.x;
    int lane = tid & 31;
    int wid = tid >> 5;

    #pragma unroll
    for (int it = 0; it < 4; it++) {
        int k = tid * 4 + it * 1024;
        *(float4*)&sS[k] = *(const float4*)&S0[(size_t)b * NK + k];
    }
    s_r[tid]       = T[(size_t)b * ND + tid];
    s_r[tid + 256] = T[(size_t)b * ND + tid + 256];
    __syncthreads();

    int kp = 0; float cp = 0.f;
    float tn = 0.f;
    double dd = 1.0;

    for (int t = 0; t < NL; t++) {
        dd *= 0.95;                 // double cumprod (same bits as before)
        float decay = (float)dd;

        // ---- phase 1: residual update + fp64 sumsq (identical ops) -------
        double ss = 0.0;
        #pragma unroll
        for (int i = 0; i < 2; i++) {
            int d = tid + i * 256;
            float r = s_r[d];
            if (cp != 0.f) {
                float c = __ldg(&Cb[(size_t)kp * ND + d]);
                r = __fsub_rn(r, __fmul_rn(cp, c));   // unfused: matches jax
                s_r[d] = r;
            }
            s_q[d] = r;
            ss += (double)r * (double)r;
        }
        #pragma unroll
        for (int o = 16; o > 0; o >>= 1)
            ss += __shfl_down_sync(0xffffffffu, ss, o);
        if (lane == 0) s_red[wid] = ss;

        // ---- phase 2: S update (fmaf, identical) + packed-u64 top-2 ------
        unsigned long long p1 = 0ull, p2 = 0ull;
        const float* grow = G + (size_t)kp * NK;
        #pragma unroll
        for (int it = 0; it < 4; it++) {
            int k = tid * 4 + it * 1024;
            float4 s4 = *(float4*)&sS[k];
            if (cp != 0.f) {
                float4 g4 = __ldg((const float4*)&grow[k]);
                s4.x = fmaf(-cp, g4.x, s4.x);
                s4.y = fmaf(-cp, g4.y, s4.y);
                s4.z = fmaf(-cp, g4.z, s4.z);
                s4.w = fmaf(-cp, g4.w, s4.w);
                *(float4*)&sS[k] = s4;
            }
            #pragma unroll
            for (int e = 0; e < 4; e++) {
                float a = fabsf((&s4.x)[e]);
                unsigned long long u =
                    ((unsigned long long)__float_as_uint(a) << 32) |
                    (unsigned)(NK - 1 - (k + e));
                if (u > p1)      { p2 = p1; p1 = u; }
                else if (u > p2) { p2 = u; }
            }
        }
        // warp top-2 merge (butterfly)
        #pragma unroll
        for (int o = 16; o > 0; o >>= 1) {
            unsigned long long q1 = __shfl_xor_sync(0xffffffffu, p1, o);
            unsigned long long q2 = __shfl_xor_sync(0xffffffffu, p2, o);
            if (q1 > p1) { p2 = (p1 > q2) ? p1 : q2; p1 = q1; }
            else         { p2 = (p2 > q1) ? p2 : q1; }
        }
        if (lane == 0) {
            s_w64[wid * 2]     = p1;
            s_w64[wid * 2 + 1] = p2;
        }
        __syncthreads();   // B1

        // ---- rho (all threads, identical left-to-right fp64 order) ------
        double tot = s_red[0] + s_red[1] + s_red[2] + s_red[3]
                   + s_red[4] + s_red[5] + s_red[6] + s_red[7];
        float rho = sqrtf((float)tot);
        if (t == 0) tn = rho;

        // ---- top-4 candidate select (single thread) ----------------------
        if (tid == 0) {
            unsigned used = 0;
            #pragma unroll
            for (int c = 0; c < 4; c++) {
                unsigned long long best = 0ull; int bi = 0;
                #pragma unroll
                for (int i = 0; i < 16; i++) {
                    if (!((used >> i) & 1u) && s_w64[i] > best) {
                        best = s_w64[i]; bi = i;
                    }
                }
                used |= 1u << bi;
                s_cand[c] = (NK - 1) - (int)(unsigned)(best & 0xffffffffull);
            }
        }
        __syncthreads();   // B2

        // ---- q-divide (identical) + stage 4 candidate rows ---------------
        {
            float den = fmaxf(rho, 1e-12f);
            int c0 = s_cand[0], c1 = s_cand[1], c2 = s_cand[2], c3 = s_cand[3];
            #pragma unroll
            for (int i = 0; i < 2; i++) {
                int d = tid + i * 256;
                s_q[d] = __fdiv_rn(s_q[d], den);
                s_cr[0][d] = __ldg(&Cb[(size_t)c0 * ND + d]);
                s_cr[1][d] = __ldg(&Cb[(size_t)c1 * ND + d]);
                s_cr[2][d] = __ldg(&Cb[(size_t)c2 * ND + d]);
                s_cr[3][d] = __ldg(&Cb[(size_t)c3 * ND + d]);
            }
        }
        __syncthreads();   // B3

        // ---- rescore (byte-identical sequential fp32 fmaf chains) --------
        float accd = 0.f;
        if (tid < 4) {
            const float* crow = s_cr[tid];
            #pragma unroll 8
            for (int d = 0; d < ND; d++)
                accd = fmaf(s_q[d], crow[d], accd);
        }
        if (wid == 0) {
            float d0 = __shfl_sync(0xffffffffu, accd, 0);
            float d1 = __shfl_sync(0xffffffffu, accd, 1);
            float d2 = __shfl_sync(0xffffffffu, accd, 2);
            float d3 = __shfl_sync(0xffffffffu, accd, 3);
            if (lane == 0) {
                float dots[4] = {d0, d1, d2, d3};
                int bk = s_cand[0]; float sb = dots[0]; float ab = fabsf(sb);
                #pragma unroll
                for (int j = 1; j < 4; j++) {
                    float aj = fabsf(dots[j]); int kj = s_cand[j];
                    if (aj > ab || (aj == ab && kj < bk)) {
                        ab = aj; sb = dots[j]; bk = kj;
                    }
                }
                bool active = (rho >= 0.01f) && (tn >= 1e-8f);
                float sgn = (sb >= 0.f) ? 1.f : -1.f;
                int sidx  = (sb >= 0.f) ? bk : -(bk + 1);
                out[b * NL + t]           = (float)(active ? sidx : 0);
                out[NB * NL + b * NL + t] = active ? 1.f : 0.f;
                s_k = bk;
                s_coef = active ? __fmul_rn(sgn, decay) : 0.f;
            }
        }
        __syncthreads();   // B4
        kp = s_k;
        cp = s_coef;
    }

    // ---- epilogue: apply FINAL step's contribution (identical ops) -------
    float r0 = s_r[tid];
    float r1 = s_r[tid + 256];
    if (cp != 0.f) {
        float c0 = __ldg(&Cb[(size_t)kp * ND + tid]);
        float c1 = __ldg(&Cb[(size_t)kp * ND + tid + 256]);
        r0 = __fsub_rn(r0, __fmul_rn(cp, c0));
        r1 = __fsub_rn(r1, __fmul_rn(cp, c1));
    }
    float* out_res = out + (size_t)2 * NB * NL;
    out_res[(size_t)b * ND + tid]       = r0;
    out_res[(size_t)b * ND + tid + 256] = r1;
}

// ---------------- launch ----------------------------------------------------
extern "C" void kernel_launch(void* const* d_in, const int* in_sizes, int n_in,
                              void* d_out, int out_size) {
    const float* targets  = (const float*)d_in[0];  // [8192, 512]
    const float* codebook = (const float*)d_in[1];  // [4096, 512]
    float* out = (float*)d_out;

    float *pS, *pG;
    cudaGetSymbolAddress((void**)&pS, g_S);
    cudaGetSymbolAddress((void**)&pG, g_G);

    dim3 gS(NK / TBN, NB / TBM);
    tf32_gemm_nt<<<gS, 256>>>(targets, codebook, pS, NB, NK, ND);

    dim3 gG(NK / TBN, NK / TBM);
    tf32_gemm_nt<<<gG, 256>>>(codebook, codebook, pG, NK, NK, ND);

    pursuit_kernel<<<NB, 256>>>(targets, codebook, pG, pS, out);
}